// round 15
// baseline (speedup 1.0000x reference)
#include <cuda_runtime.h>
#include <cuda_bf16.h>
#include <cstdint>

#define BB 16
#define LL 2048
#define HH 768
#define DD 64
#define VV 30000
#define CC 128               // chunk length
#define NC 16                // number of chunks

// ---------------------------------------------------------------------------
// Device-global scratch (Xt buffers deleted)
// ---------------------------------------------------------------------------
__device__ __nv_bfloat16 g_Eph[(size_t)BB * LL * DD];
__device__ __nv_bfloat16 g_Epl[(size_t)BB * LL * DD];
__device__ __nv_bfloat16 g_Fph[(size_t)BB * LL * DD];
__device__ __nv_bfloat16 g_Fpl[(size_t)BB * LL * DD];
__device__ __nv_bfloat16 g_Fth[(size_t)BB * DD * LL];
__device__ __nv_bfloat16 g_Ftl[(size_t)BB * DD * LL];
__device__ float         g_T [(size_t)BB * NC * HH * DD];
__device__ __nv_bfloat16 g_Sh[(size_t)BB * NC * HH * DD];
__device__ __nv_bfloat16 g_Sl[(size_t)BB * NC * HH * DD];
__device__ __nv_bfloat16 g_Ph[(size_t)BB * NC * CC * CC];
__device__ __nv_bfloat16 g_Pl[(size_t)BB * NC * CC * CC];

// ---------------------------------------------------------------------------
// helpers
// ---------------------------------------------------------------------------
__device__ __forceinline__ uint32_t smem_u32(const void* p) {
    uint32_t a;
    asm("{ .reg .u64 t; cvta.to.shared.u64 t, %1; cvt.u32.u64 %0, t; }"
        : "=r"(a) : "l"(p));
    return a;
}
__device__ __forceinline__ void ldm_x4(uint32_t& r0, uint32_t& r1, uint32_t& r2,
                                       uint32_t& r3, uint32_t addr) {
    asm volatile("ldmatrix.sync.aligned.m8n8.x4.shared.b16 {%0,%1,%2,%3}, [%4];"
                 : "=r"(r0), "=r"(r1), "=r"(r2), "=r"(r3) : "r"(addr));
}
__device__ __forceinline__ void ldm_x4_t(uint32_t& r0, uint32_t& r1, uint32_t& r2,
                                         uint32_t& r3, uint32_t addr) {
    asm volatile("ldmatrix.sync.aligned.m8n8.x4.trans.shared.b16 {%0,%1,%2,%3}, [%4];"
                 : "=r"(r0), "=r"(r1), "=r"(r2), "=r"(r3) : "r"(addr));
}
__device__ __forceinline__ void mma16816(float* c, uint32_t a0, uint32_t a1,
                                         uint32_t a2, uint32_t a3, uint32_t b0,
                                         uint32_t b1) {
    asm volatile(
        "mma.sync.aligned.m16n8k16.row.col.f32.bf16.bf16.f32 "
        "{%0,%1,%2,%3}, {%4,%5,%6,%7}, {%8,%9}, {%0,%1,%2,%3};"
        : "+f"(c[0]), "+f"(c[1]), "+f"(c[2]), "+f"(c[3])
        : "r"(a0), "r"(a1), "r"(a2), "r"(a3), "r"(b0), "r"(b1));
}
__device__ __forceinline__ void cp16(uint32_t s, const void* g) {
    asm volatile("cp.async.cg.shared.global [%0], [%1], 16;" :: "r"(s), "l"(g));
}
#define CP_COMMIT()  asm volatile("cp.async.commit_group;" ::: "memory")
#define CP_WAIT(n)   asm volatile("cp.async.wait_group %0;" :: "n"(n) : "memory")

__device__ __forceinline__ void split2pack(float a, float b, uint32_t& hi,
                                           uint32_t& lo) {
    __nv_bfloat16 ha = __float2bfloat16(a), hb = __float2bfloat16(b);
    __nv_bfloat16 la = __float2bfloat16(a - __bfloat162float(ha));
    __nv_bfloat16 lb = __float2bfloat16(b - __bfloat162float(hb));
    hi = (uint32_t)__bfloat16_as_ushort(ha) |
         ((uint32_t)__bfloat16_as_ushort(hb) << 16);
    lo = (uint32_t)__bfloat16_as_ushort(la) |
         ((uint32_t)__bfloat16_as_ushort(lb) << 16);
}

#define STRB  144
#define TILE  18432
#define STRP  272   // also the [i][h] bf16-tile stride (256B data + 16 pad)
#define PTILE 34816

// normal GEMM: A K-major (stride via aMstr/32B ksteps), B K-major
template <int MF>
__device__ __forceinline__ void gemm4t(float (&acc)[MF][4][4], uint32_t aH,
                                       uint32_t aL, uint32_t bH, uint32_t bL,
                                       uint32_t aMstr) {
#pragma unroll
    for (int s = 0; s < 4; s++) {
        uint32_t ks = (uint32_t)(s * 32);
        uint32_t bhf[8], blf[8];
        ldm_x4(bhf[0], bhf[1], bhf[2], bhf[3], bH + ks);
        ldm_x4(bhf[4], bhf[5], bhf[6], bhf[7], bH + ks + 16 * STRB);
        ldm_x4(blf[0], blf[1], blf[2], blf[3], bL + ks);
        ldm_x4(blf[4], blf[5], blf[6], blf[7], bL + ks + 16 * STRB);
#pragma unroll
        for (int m = 0; m < MF; m++) {
            uint32_t ah0, ah1, ah2, ah3, al0, al1, al2, al3;
            ldm_x4(ah0, ah1, ah2, ah3, aH + m * aMstr + ks);
            ldm_x4(al0, al1, al2, al3, aL + m * aMstr + ks);
#pragma unroll
            for (int n = 0; n < 4; n++) {
                uint32_t i0 = (uint32_t)((n >> 1) * 4 + (n & 1) * 2);
                mma16816(acc[m][n], ah0, ah1, ah2, ah3, bhf[i0], bhf[i0 + 1]);
                mma16816(acc[m][n], ah0, ah1, ah2, ah3, blf[i0], blf[i0 + 1]);
                mma16816(acc[m][n], al0, al1, al2, al3, bhf[i0], bhf[i0 + 1]);
            }
        }
    }
}

// B via trans-ldmatrix from [k][n] storage (stride STRP). A normal.
template <int MF>
__device__ __forceinline__ void gemm4_bt(float (&acc)[MF][4][4], uint32_t aH,
                                         uint32_t aL, uint32_t bH, uint32_t bL,
                                         uint32_t aMstr) {
#pragma unroll
    for (int s = 0; s < 4; s++) {
        uint32_t ksA = (uint32_t)(s * 32);
        uint32_t ksB = (uint32_t)(s * 16 * STRP);
        uint32_t bhf[8], blf[8];
        ldm_x4_t(bhf[0], bhf[1], bhf[2], bhf[3], bH + ksB);
        ldm_x4_t(bhf[4], bhf[5], bhf[6], bhf[7], bH + ksB + 32);
        ldm_x4_t(blf[0], blf[1], blf[2], blf[3], bL + ksB);
        ldm_x4_t(blf[4], blf[5], blf[6], blf[7], bL + ksB + 32);
#pragma unroll
        for (int m = 0; m < MF; m++) {
            uint32_t ah0, ah1, ah2, ah3, al0, al1, al2, al3;
            ldm_x4(ah0, ah1, ah2, ah3, aH + m * aMstr + ksA);
            ldm_x4(al0, al1, al2, al3, aL + m * aMstr + ksA);
#pragma unroll
            for (int n = 0; n < 4; n++) {
                uint32_t i0 = (uint32_t)((n >> 1) * 4 + (n & 1) * 2);
                mma16816(acc[m][n], ah0, ah1, ah2, ah3, bhf[i0], bhf[i0 + 1]);
                mma16816(acc[m][n], ah0, ah1, ah2, ah3, blf[i0], blf[i0 + 1]);
                mma16816(acc[m][n], al0, al1, al2, al3, bhf[i0], bhf[i0 + 1]);
            }
        }
    }
}

// A via trans-ldmatrix from [k][m] storage (stride STRP, m-step 32B). B normal.
template <int MF>
__device__ __forceinline__ void gemm4_at(float (&acc)[MF][4][4], uint32_t aH,
                                         uint32_t aL, uint32_t bH, uint32_t bL) {
#pragma unroll
    for (int s = 0; s < 4; s++) {
        uint32_t ksA = (uint32_t)(s * 16 * STRP);
        uint32_t ksB = (uint32_t)(s * 32);
        uint32_t bhf[8], blf[8];
        ldm_x4(bhf[0], bhf[1], bhf[2], bhf[3], bH + ksB);
        ldm_x4(bhf[4], bhf[5], bhf[6], bhf[7], bH + ksB + 16 * STRB);
        ldm_x4(blf[0], blf[1], blf[2], blf[3], bL + ksB);
        ldm_x4(blf[4], blf[5], blf[6], blf[7], bL + ksB + 16 * STRB);
#pragma unroll
        for (int m = 0; m < MF; m++) {
            uint32_t ah0, ah1, ah2, ah3, al0, al1, al2, al3;
            ldm_x4_t(ah0, ah1, ah2, ah3, aH + m * 32 + ksA);
            ldm_x4_t(al0, al1, al2, al3, aL + m * 32 + ksA);
#pragma unroll
            for (int n = 0; n < 4; n++) {
                uint32_t i0 = (uint32_t)((n >> 1) * 4 + (n & 1) * 2);
                mma16816(acc[m][n], ah0, ah1, ah2, ah3, bhf[i0], bhf[i0 + 1]);
                mma16816(acc[m][n], ah0, ah1, ah2, ah3, blf[i0], blf[i0 + 1]);
                mma16816(acc[m][n], al0, al1, al2, al3, bhf[i0], bhf[i0 + 1]);
            }
        }
    }
}

// ---------------------------------------------------------------------------
// K1: E=ae[x], F=E@w; E'=E/(l+1), F'=F*(l+1); split+store. 64 rows/CTA.
// ---------------------------------------------------------------------------
__global__ void __launch_bounds__(256) k_prep(const float* __restrict__ ae,
                                              const void* __restrict__ xraw,
                                              const float* __restrict__ w) {
    __shared__ float ws[64 * 64];
    __shared__ float es[4][64];
    __shared__ __nv_bfloat16 fth[64][66];
    __shared__ __nv_bfloat16 ftl[64][66];
    for (int t = threadIdx.x; t < 64 * 64; t += 256) ws[t] = w[t];

    const int* xi = (const int*)xraw;
    bool is64 = true;
#pragma unroll
    for (int k = 0; k < 32; k++)
        if (xi[2 * k + 1] != 0) is64 = false;

    int sub = threadIdx.x >> 6;
    int d   = threadIdx.x & 63;

    int rowBase = blockIdx.x * 64;
    int b  = rowBase >> 11;
    int l0 = rowBase & (LL - 1);

    for (int it = 0; it < 16; it++) {
        int lloc = it * 4 + sub;
        int row = rowBase + lloc;
        int l = l0 + lloc;

        long long tok;
        if (is64) tok = ((const long long*)xraw)[row];
        else      tok = (long long)xi[row];
        if (tok < 0) tok = 0;
        if (tok >= VV) tok = VV - 1;

        float e = ae[(size_t)tok * 64 + d];
        __syncthreads();
        es[sub][d] = e;
        __syncthreads();
        float f = 0.f;
#pragma unroll
        for (int k = 0; k < 64; k++) f += es[sub][k] * ws[k * 64 + d];

        float sc = (float)(l + 1);
        float ep = e / sc;
        float fp = f * sc;

        __nv_bfloat16 eh = __float2bfloat16(ep);
        __nv_bfloat16 el = __float2bfloat16(ep - __bfloat162float(eh));
        __nv_bfloat16 fh = __float2bfloat16(fp);
        __nv_bfloat16 fl = __float2bfloat16(fp - __bfloat162float(fh));

        size_t ro = (size_t)row * 64 + d;
        g_Eph[ro] = eh; g_Epl[ro] = el;
        g_Fph[ro] = fh; g_Fpl[ro] = fl;
        fth[d][lloc] = fh;
        ftl[d][lloc] = fl;
    }
    __syncthreads();

    for (int k = 0; k < 8; k++) {
        int idx = k * 256 + threadIdx.x;
        int dd = idx >> 5, lw = idx & 31;
        uint32_t vh = (uint32_t)__bfloat16_as_ushort(fth[dd][lw * 2]) |
                      ((uint32_t)__bfloat16_as_ushort(fth[dd][lw * 2 + 1]) << 16);
        uint32_t vl = (uint32_t)__bfloat16_as_ushort(ftl[dd][lw * 2]) |
                      ((uint32_t)__bfloat16_as_ushort(ftl[dd][lw * 2 + 1]) << 16);
        size_t to = ((size_t)b * 64 + dd) * LL + l0 + lw * 2;
        *(uint32_t*)&g_Fth[to] = vh;
        *(uint32_t*)&g_Ftl[to] = vl;
    }
}

// ---------------------------------------------------------------------------
// FAT2: pgen (CTAs 0..255) ∪ chunksum (CTAs 256..1791). 256 threads.
// ---------------------------------------------------------------------------
#define PG_SMEM (4 * TILE)

__device__ void do_pgen(char* smem, int cta) {
    uint32_t sb = smem_u32(smem);
    int tid = threadIdx.x, wid = tid >> 5, l = tid & 31;
    int c = cta & (NC - 1), b = cta >> 4;
    int jBase = c * CC;
    int wm = wid & 1, wn = wid >> 1;
    int fRow = tid >> 3, fCol = tid & 7;
    uint32_t fOff = (uint32_t)(fRow * STRB + fCol * 16);

    size_t eBase = ((size_t)b * LL + jBase) * 64;
#pragma unroll
    for (int v = 0; v < 4; v++) {
        uint32_t so = fOff + (uint32_t)(v * 32 * STRB);
        size_t go = eBase + (size_t)(fRow + v * 32) * 64 + fCol * 8;
        cp16(sb + 0 * TILE + so, g_Eph + go);
        cp16(sb + 1 * TILE + so, g_Epl + go);
        cp16(sb + 2 * TILE + so, g_Fph + go);
        cp16(sb + 3 * TILE + so, g_Fpl + go);
    }
    CP_COMMIT();
    CP_WAIT(0);
    __syncthreads();

    uint32_t aLane = (uint32_t)((wm * 64 + (l & 15)) * STRB + (l >> 4) * 16);
    uint32_t xLane = (uint32_t)((wn * 32 + (l & 7) + ((l >> 4) * 8)) * STRB +
                                ((l >> 3) & 1) * 16);

    float acc[4][4][4];
#pragma unroll
    for (int m = 0; m < 4; m++)
#pragma unroll
        for (int n = 0; n < 4; n++)
#pragma unroll
            for (int k = 0; k < 4; k++) acc[m][n][k] = 0.f;

    gemm4t<4>(acc, sb + 0 * TILE + aLane, sb + 1 * TILE + aLane,
              sb + 2 * TILE + xLane, sb + 3 * TILE + xLane, 16 * STRB);

    __nv_bfloat16* Ph = g_Ph + ((size_t)(b * NC + c)) * CC * CC;
    __nv_bfloat16* Pl = g_Pl + ((size_t)(b * NC + c)) * CC * CC;
#pragma unroll
    for (int m = 0; m < 4; m++) {
#pragma unroll
        for (int n = 0; n < 4; n++) {
            int gm = wm * 64 + m * 16 + (l >> 2);
            int gn = wn * 32 + n * 8 + (l & 3) * 2;
            float v0 = (gn < gm) ? acc[m][n][0] : 0.f;
            float v1 = (gn + 1 < gm) ? acc[m][n][1] : 0.f;
            float v2 = (gn < gm + 8) ? acc[m][n][2] : 0.f;
            float v3 = (gn + 1 < gm + 8) ? acc[m][n][3] : 0.f;
            uint32_t hi, lo;
            split2pack(v0, v1, hi, lo);
            *(uint32_t*)(Ph + (size_t)gm * CC + gn) = hi;
            *(uint32_t*)(Pl + (size_t)gm * CC + gn) = lo;
            split2pack(v2, v3, hi, lo);
            *(uint32_t*)(Ph + (size_t)(gm + 8) * CC + gn) = hi;
            *(uint32_t*)(Pl + (size_t)(gm + 8) * CC + gn) = lo;
        }
    }
}

// chunksum smem layout: Xbf slabs (64 rows x 272B) x2 stages + F slabs x2
#define CS_XH(s) ((s) * 17408 * 2)
#define CS_XL(s) ((s) * 17408 * 2 + 17408)
#define CS_FH(s) (69632 + (s) * 18432)
#define CS_FL(s) (69632 + (s) * 18432 + 9216)
#define CS_SMEM  106496

__device__ void do_chunksum(char* smem, int cta, const float* __restrict__ bx) {
    uint32_t sb = smem_u32(smem);
    int tid = threadIdx.x, wid = tid >> 5, l = tid & 31;
    int hT = cta % 6;
    int c  = (cta / 6) & (NC - 1);
    int b  = cta / (6 * NC);
    int hBase = hT * 128;
    int wm = wid & 3, wn = wid >> 2;

    // F fills (both stages)
    {
        int fRow = tid >> 3, fCol = tid & 7;
        uint32_t fOff = (uint32_t)(fRow * STRB + fCol * 16);
#pragma unroll
        for (int st = 0; st < 2; st++) {
            size_t kOff = (size_t)c * CC + st * 64;
#pragma unroll
            for (int v = 0; v < 2; v++) {
                int idx = v * 256 + tid;
                int row = idx >> 3, col = idx & 7;
                uint32_t so = (uint32_t)(row * STRB + col * 16);
                size_t go = ((size_t)(b * DD + row)) * LL + kOff + col * 8;
                cp16(sb + CS_FH(st) + so, g_Fth + go);
                cp16(sb + CS_FL(st) + so, g_Ftl + go);
            }
            CP_COMMIT();
        }
        (void)fOff;
    }

    // convert slab st: bx[i = c*128+st*64 .. +64][hBase..+128] -> bf16 [i][h]
#define CS_CONVERT(ST)                                                            \
    do {                                                                          \
        _Pragma("unroll")                                                         \
        for (int _v = 0; _v < 8; _v++) {                                          \
            int _idx = _v * 256 + tid;                                            \
            int _i = _idx >> 5, _c4 = _idx & 31;                                  \
            float4 _f = *((const float4*)(bx +                                    \
                ((size_t)b * LL + (size_t)c * CC + (ST) * 64 + _i) * HH + hBase)  \
                + _c4);                                                           \
            uint32_t _h0, _l0, _h1, _l1;                                          \
            split2pack(_f.x, _f.y, _h0, _l0);                                     \
            split2pack(_f.z, _f.w, _h1, _l1);                                     \
            uint32_t _ro = (uint32_t)(_i * STRP + _c4 * 8);                       \
            *(uint2*)(smem + CS_XH(ST) + _ro) = make_uint2(_h0, _h1);             \
            *(uint2*)(smem + CS_XL(ST) + _ro) = make_uint2(_l0, _l1);             \
        }                                                                         \
    } while (0)

    CS_CONVERT(0);

    // lane maps
    uint32_t atLane = (uint32_t)(((l & 7) + ((l >> 4) * 8)) * STRP +
                                 ((l >> 3) & 1) * 16 + wm * 64);
    uint32_t xLane  = (uint32_t)((wn * 32 + (l & 7) + ((l >> 4) * 8)) * STRB +
                                 ((l >> 3) & 1) * 16);

    float acc[2][4][4];
#pragma unroll
    for (int m = 0; m < 2; m++)
#pragma unroll
        for (int n = 0; n < 4; n++)
#pragma unroll
            for (int k = 0; k < 4; k++) acc[m][n][k] = 0.f;

    CP_WAIT(1);          // F0 done
    __syncthreads();     // publishes convert0 STS
    gemm4_at<2>(acc, sb + CS_XH(0) + atLane, sb + CS_XL(0) + atLane,
                sb + CS_FH(0) + xLane, sb + CS_FL(0) + xLane);

    CS_CONVERT(1);
    CP_WAIT(0);          // F1 done
    __syncthreads();     // publishes convert1 STS
    gemm4_at<2>(acc, sb + CS_XH(1) + atLane, sb + CS_XL(1) + atLane,
                sb + CS_FH(1) + xLane, sb + CS_FL(1) + xLane);
#undef CS_CONVERT

    float* Tp = g_T + ((size_t)(b * NC + c)) * HH * DD;
#pragma unroll
    for (int m = 0; m < 2; m++) {
#pragma unroll
        for (int n = 0; n < 4; n++) {
            int gm = hBase + wm * 32 + m * 16 + (l >> 2);
            int gn = wn * 32 + n * 8 + (l & 3) * 2;
            *(float2*)(Tp + (size_t)gm * 64 + gn) =
                make_float2(acc[m][n][0], acc[m][n][1]);
            *(float2*)(Tp + (size_t)(gm + 8) * 64 + gn) =
                make_float2(acc[m][n][2], acc[m][n][3]);
        }
    }
}

__global__ void __launch_bounds__(256) k_fat2(const float* __restrict__ bx) {
    extern __shared__ char smem[];
    int cta = blockIdx.x;
    if (cta < 256) do_pgen(smem, cta);
    else           do_chunksum(smem, cta - 256, bx);
}

// ---------------------------------------------------------------------------
// K3: exclusive prefix over chunks (float4 per thread)
// ---------------------------------------------------------------------------
__global__ void __launch_bounds__(256) k_prefix() {
    int b = blockIdx.y;
    int hd = (blockIdx.x * 256 + threadIdx.x) * 4;
    float4 run = make_float4(0.f, 0.f, 0.f, 0.f);
#pragma unroll
    for (int c = 0; c < NC; c++) {
        size_t o = ((size_t)(b * NC + c)) * HH * DD + hd;
        uint32_t h0, l0, h1, l1;
        split2pack(run.x, run.y, h0, l0);
        split2pack(run.z, run.w, h1, l1);
        *(uint2*)&g_Sh[o] = make_uint2(h0, h1);
        *(uint2*)&g_Sl[o] = make_uint2(l0, l1);
        float4 t = *(const float4*)&g_T[o];
        run.x += t.x; run.y += t.y; run.z += t.z; run.w += t.w;
    }
}

// ---------------------------------------------------------------------------
// K4: 512 threads. X tiles built in-kernel from bx via convert + trans-ldmatrix.
// ---------------------------------------------------------------------------
#define OFF_EH  0
#define OFF_EL  TILE
#define OFF_SH  (2 * TILE)
#define OFF_SL  (3 * TILE)
#define OFF_PH  (4 * TILE)
#define OFF_PL  (4 * TILE + PTILE)
#define OFF_XH  (4 * TILE + 2 * PTILE)
#define OFF_XL  (4 * TILE + 3 * PTILE)
#define K4_SMEM (4 * TILE + 4 * PTILE)   // 212992

__global__ void __launch_bounds__(512, 1) k_apply2(const float* __restrict__ bx,
                                                   float* __restrict__ out) {
    extern __shared__ char smem[];
    uint32_t sb = smem_u32(smem);
    int tid = threadIdx.x, wid = tid >> 5, l = tid & 31;
    int hT = blockIdx.x, c = blockIdx.y, b = blockIdx.z;
    int hBase = hT * 128, jBase = c * CC;
    int wm = wid & 3, wn = wid >> 2;

    int fRow = tid >> 3, fCol = tid & 7;
    uint32_t fOff = (uint32_t)(fRow * STRB + fCol * 16);

    // G0: E' + S
    {
        size_t eBase = ((size_t)b * LL + jBase) * 64;
        size_t sBase = (((size_t)(b * NC + c)) * HH + hBase) * 64;
#pragma unroll
        for (int v = 0; v < 2; v++) {
            uint32_t so = fOff + (uint32_t)(v * 64 * STRB);
            size_t ge = eBase + (size_t)(fRow + v * 64) * 64 + fCol * 8;
            size_t gs = sBase + (size_t)(fRow + v * 64) * 64 + fCol * 8;
            cp16(sb + OFF_EH + so, g_Eph + ge);
            cp16(sb + OFF_EL + so, g_Epl + ge);
            cp16(sb + OFF_SH + so, g_Sh + gs);
            cp16(sb + OFF_SL + so, g_Sl + gs);
        }
        CP_COMMIT();
    }
    // G1: P (hi/lo)
    {
        const __nv_bfloat16* Ph = g_Ph + ((size_t)(b * NC + c)) * CC * CC;
        const __nv_bfloat16* Pl = g_Pl + ((size_t)(b * NC + c)) * CC * CC;
#pragma unroll
        for (int v = 0; v < 4; v++) {
            int idx = v * 512 + tid;
            int row = idx >> 4, col = idx & 15;
            uint32_t so = (uint32_t)(row * STRP + col * 16);
            size_t go = (size_t)row * CC + col * 8;
            cp16(sb + OFF_PH + so, Ph + go);
            cp16(sb + OFF_PL + so, Pl + go);
        }
        CP_COMMIT();
    }

    // Convert: bx[jBase+i][hBase+h] fp32 -> bf16 hi/lo [i][h] tiles (128x128)
#pragma unroll
    for (int v = 0; v < 8; v++) {
        int idx = v * 512 + tid;
        int i = idx >> 5, c4 = idx & 31;
        float4 f = *((const float4*)(bx + ((size_t)b * LL + jBase + i) * HH + hBase) + c4);
        uint32_t h0, l0, h1, l1;
        split2pack(f.x, f.y, h0, l0);
        split2pack(f.z, f.w, h1, l1);
        uint32_t ro = (uint32_t)(i * STRP + c4 * 8);
        *(uint2*)(smem + OFF_XH + ro) = make_uint2(h0, h1);
        *(uint2*)(smem + OFF_XL + ro) = make_uint2(l0, l1);
    }

    uint32_t aLane  = (uint32_t)((wm * 32 + (l & 15)) * STRB + (l >> 4) * 16);
    uint32_t aLaneP = (uint32_t)((wm * 32 + (l & 15)) * STRP + (l >> 4) * 16);
    uint32_t xLane  = (uint32_t)((wn * 32 + (l & 7) + ((l >> 4) * 8)) * STRB +
                                 ((l >> 3) & 1) * 16);
    uint32_t btLane = (uint32_t)(((l & 7) + ((l >> 3) & 1) * 8) * STRP +
                                 (l >> 4) * 16 + wn * 64);

    float acc[2][4][4];
#pragma unroll
    for (int m = 0; m < 2; m++)
#pragma unroll
        for (int n = 0; n < 4; n++)
#pragma unroll
            for (int k = 0; k < 4; k++) acc[m][n][k] = 0.f;

    // ---- C1: acc += E' @ S^T ----
    CP_WAIT(1);          // G0 done (P may pend)
    __syncthreads();     // also publishes convert STS
    gemm4t<2>(acc, sb + OFF_EH + aLane, sb + OFF_EL + aLane,
              sb + OFF_SH + xLane, sb + OFF_SL + xLane, 16 * STRB);

    // ---- C2a: acc += P[:,0:64] @ X[0:64]^T ----
    CP_WAIT(0);          // P done
    __syncthreads();
    gemm4_bt<2>(acc, sb + OFF_PH + aLaneP, sb + OFF_PL + aLaneP,
                sb + OFF_XH + btLane, sb + OFF_XL + btLane, 16 * STRP);

    // ---- C2b: acc += P[:,64:128] @ X[64:128]^T ---- (no sync needed: reads only)
    gemm4_bt<2>(acc, sb + OFF_PH + aLaneP + 128, sb + OFF_PL + aLaneP + 128,
                sb + OFF_XH + btLane + 64 * STRP, sb + OFF_XL + btLane + 64 * STRP,
                16 * STRP);

    // ---- epilogue ----
#pragma unroll
    for (int m = 0; m < 2; m++) {
#pragma unroll
        for (int n = 0; n < 4; n++) {
            int gj = jBase + wm * 32 + m * 16 + (l >> 2);
            int gh = hBase + wn * 32 + n * 8 + (l & 3) * 2;
            size_t o0 = ((size_t)b * LL + gj) * HH + gh;
            size_t o1 = ((size_t)b * LL + gj + 8) * HH + gh;
            float2 x0 = *(const float2*)(bx + o0);
            float2 x1 = *(const float2*)(bx + o1);
            *(float2*)(out + o0) = make_float2(x0.x + acc[m][n][0], x0.y + acc[m][n][1]);
            *(float2*)(out + o1) = make_float2(x1.x + acc[m][n][2], x1.y + acc[m][n][3]);
        }
    }
}

// ---------------------------------------------------------------------------
extern "C" void kernel_launch(void* const* d_in, const int* in_sizes, int n_in,
                              void* d_out, int out_size) {
    const float* bert_x = nullptr;
    const void*  x      = nullptr;
    const float* ae     = nullptr;
    const float* w      = nullptr;
    for (int i = 0; i < n_in; i++) {
        switch (in_sizes[i]) {
            case 25165824: bert_x = (const float*)d_in[i]; break;
            case 32768:    x      = d_in[i];               break;
            case 1920000:  ae     = (const float*)d_in[i]; break;
            case 4096:     w      = (const float*)d_in[i]; break;
            default: break;
        }
    }
    float* out = (float*)d_out;

    int fat2_smem = PG_SMEM > CS_SMEM ? PG_SMEM : CS_SMEM;
    cudaFuncSetAttribute(k_fat2,
                         cudaFuncAttributeMaxDynamicSharedMemorySize, fat2_smem);
    cudaFuncSetAttribute(k_apply2,
                         cudaFuncAttributeMaxDynamicSharedMemorySize, K4_SMEM);

    k_prep<<<512, 256>>>(ae, x, w);
    k_fat2<<<256 + 1536, 256, fat2_smem>>>(bert_x);
    k_prefix<<<dim3(HH * DD / 1024, BB), 256>>>();
    k_apply2<<<dim3(HH / 128, NC, BB), 512, K4_SMEM>>>(bert_x, out);
}

// round 16
// speedup vs baseline: 1.0234x; 1.0234x over previous
#include <cuda_runtime.h>
#include <cuda_bf16.h>
#include <cstdint>

#define BB 16
#define LL 2048
#define HH 768
#define DD 64
#define VV 30000
#define CC 128               // chunk length
#define NC 16                // number of chunks

// ---------------------------------------------------------------------------
// Device-global scratch
// ---------------------------------------------------------------------------
__device__ __nv_bfloat16 g_Eph[(size_t)BB * LL * DD];
__device__ __nv_bfloat16 g_Epl[(size_t)BB * LL * DD];
__device__ __nv_bfloat16 g_Fph[(size_t)BB * LL * DD];
__device__ __nv_bfloat16 g_Fpl[(size_t)BB * LL * DD];
__device__ __nv_bfloat16 g_Fth[(size_t)BB * DD * LL];
__device__ __nv_bfloat16 g_Ftl[(size_t)BB * DD * LL];
__device__ __nv_bfloat16 g_Xh[(size_t)BB * HH * LL];
__device__ __nv_bfloat16 g_Xl[(size_t)BB * HH * LL];
__device__ float         g_T [(size_t)BB * NC * HH * DD];
__device__ __nv_bfloat16 g_Sh[(size_t)BB * NC * HH * DD];
__device__ __nv_bfloat16 g_Sl[(size_t)BB * NC * HH * DD];
__device__ __nv_bfloat16 g_Ph[(size_t)BB * NC * CC * CC];
__device__ __nv_bfloat16 g_Pl[(size_t)BB * NC * CC * CC];

// ---------------------------------------------------------------------------
// helpers
// ---------------------------------------------------------------------------
__device__ __forceinline__ uint32_t smem_u32(const void* p) {
    uint32_t a;
    asm("{ .reg .u64 t; cvta.to.shared.u64 t, %1; cvt.u32.u64 %0, t; }"
        : "=r"(a) : "l"(p));
    return a;
}
__device__ __forceinline__ void ldm_x4(uint32_t& r0, uint32_t& r1, uint32_t& r2,
                                       uint32_t& r3, uint32_t addr) {
    asm volatile("ldmatrix.sync.aligned.m8n8.x4.shared.b16 {%0,%1,%2,%3}, [%4];"
                 : "=r"(r0), "=r"(r1), "=r"(r2), "=r"(r3) : "r"(addr));
}
__device__ __forceinline__ void mma16816(float* c, uint32_t a0, uint32_t a1,
                                         uint32_t a2, uint32_t a3, uint32_t b0,
                                         uint32_t b1) {
    asm volatile(
        "mma.sync.aligned.m16n8k16.row.col.f32.bf16.bf16.f32 "
        "{%0,%1,%2,%3}, {%4,%5,%6,%7}, {%8,%9}, {%0,%1,%2,%3};"
        : "+f"(c[0]), "+f"(c[1]), "+f"(c[2]), "+f"(c[3])
        : "r"(a0), "r"(a1), "r"(a2), "r"(a3), "r"(b0), "r"(b1));
}
__device__ __forceinline__ void cp16(uint32_t s, const void* g) {
    asm volatile("cp.async.cg.shared.global [%0], [%1], 16;" :: "r"(s), "l"(g));
}
#define CP_COMMIT()  asm volatile("cp.async.commit_group;" ::: "memory")
#define CP_WAIT(n)   asm volatile("cp.async.wait_group %0;" :: "n"(n) : "memory")

__device__ __forceinline__ void prefetchL2(const void* p) {
    asm volatile("prefetch.global.L2 [%0];" :: "l"(p));
}

__device__ __forceinline__ void split2pack(float a, float b, uint32_t& hi,
                                           uint32_t& lo) {
    __nv_bfloat16 ha = __float2bfloat16(a), hb = __float2bfloat16(b);
    __nv_bfloat16 la = __float2bfloat16(a - __bfloat162float(ha));
    __nv_bfloat16 lb = __float2bfloat16(b - __bfloat162float(hb));
    hi = (uint32_t)__bfloat16_as_ushort(ha) |
         ((uint32_t)__bfloat16_as_ushort(hb) << 16);
    lo = (uint32_t)__bfloat16_as_ushort(la) |
         ((uint32_t)__bfloat16_as_ushort(lb) << 16);
}

#define STRB  144
#define TILE  18432
#define STRP  272
#define PTILE 34816

template <int MF>
__device__ __forceinline__ void gemm4t(float (&acc)[MF][4][4], uint32_t aH,
                                       uint32_t aL, uint32_t bH, uint32_t bL,
                                       uint32_t aMstr) {
#pragma unroll
    for (int s = 0; s < 4; s++) {
        uint32_t ks = (uint32_t)(s * 32);
        uint32_t bhf[8], blf[8];
        ldm_x4(bhf[0], bhf[1], bhf[2], bhf[3], bH + ks);
        ldm_x4(bhf[4], bhf[5], bhf[6], bhf[7], bH + ks + 16 * STRB);
        ldm_x4(blf[0], blf[1], blf[2], blf[3], bL + ks);
        ldm_x4(blf[4], blf[5], blf[6], blf[7], bL + ks + 16 * STRB);
#pragma unroll
        for (int m = 0; m < MF; m++) {
            uint32_t ah0, ah1, ah2, ah3, al0, al1, al2, al3;
            ldm_x4(ah0, ah1, ah2, ah3, aH + m * aMstr + ks);
            ldm_x4(al0, al1, al2, al3, aL + m * aMstr + ks);
#pragma unroll
            for (int n = 0; n < 4; n++) {
                uint32_t i0 = (uint32_t)((n >> 1) * 4 + (n & 1) * 2);
                mma16816(acc[m][n], ah0, ah1, ah2, ah3, bhf[i0], bhf[i0 + 1]);
                mma16816(acc[m][n], ah0, ah1, ah2, ah3, blf[i0], blf[i0 + 1]);
                mma16816(acc[m][n], al0, al1, al2, al3, bhf[i0], bhf[i0 + 1]);
            }
        }
    }
}

// ---------------------------------------------------------------------------
// FAT KERNEL 1: prep (CTAs 0..511) ∪ xprep (CTAs 512..12799). 256 threads.
// ---------------------------------------------------------------------------
union SmemU1 {
    struct {
        float ws[64 * 64];
        float es[4][64];
        __nv_bfloat16 fth[64][66];
        __nv_bfloat16 ftl[64][66];
    } p;
    struct {
        float t[32][65];
    } x;
};

__device__ void do_prep(SmemU1* u, int cta, const float* __restrict__ ae,
                        const void* __restrict__ xraw, const float* __restrict__ w) {
    for (int t = threadIdx.x; t < 64 * 64; t += 256) u->p.ws[t] = w[t];

    const int* xi = (const int*)xraw;
    bool is64 = true;
#pragma unroll
    for (int k = 0; k < 32; k++)
        if (xi[2 * k + 1] != 0) is64 = false;

    int sub = threadIdx.x >> 6;
    int d   = threadIdx.x & 63;

    int rowBase = cta * 64;
    int b  = rowBase >> 11;
    int l0 = rowBase & (LL - 1);

    for (int it = 0; it < 16; it++) {
        int lloc = it * 4 + sub;
        int row = rowBase + lloc;
        int l = l0 + lloc;

        long long tok;
        if (is64) tok = ((const long long*)xraw)[row];
        else      tok = (long long)xi[row];
        if (tok < 0) tok = 0;
        if (tok >= VV) tok = VV - 1;

        float e = ae[(size_t)tok * 64 + d];
        __syncthreads();
        u->p.es[sub][d] = e;
        __syncthreads();
        float f = 0.f;
#pragma unroll
        for (int k = 0; k < 64; k++) f += u->p.es[sub][k] * u->p.ws[k * 64 + d];

        float sc = (float)(l + 1);
        float ep = e / sc;
        float fp = f * sc;

        __nv_bfloat16 eh = __float2bfloat16(ep);
        __nv_bfloat16 el = __float2bfloat16(ep - __bfloat162float(eh));
        __nv_bfloat16 fh = __float2bfloat16(fp);
        __nv_bfloat16 fl = __float2bfloat16(fp - __bfloat162float(fh));

        size_t ro = (size_t)row * 64 + d;
        g_Eph[ro] = eh; g_Epl[ro] = el;
        g_Fph[ro] = fh; g_Fpl[ro] = fl;
        u->p.fth[d][lloc] = fh;
        u->p.ftl[d][lloc] = fl;
    }
    __syncthreads();

    for (int k = 0; k < 8; k++) {
        int idx = k * 256 + threadIdx.x;
        int dd = idx >> 5, lw = idx & 31;
        uint32_t vh = (uint32_t)__bfloat16_as_ushort(u->p.fth[dd][lw * 2]) |
                      ((uint32_t)__bfloat16_as_ushort(u->p.fth[dd][lw * 2 + 1]) << 16);
        uint32_t vl = (uint32_t)__bfloat16_as_ushort(u->p.ftl[dd][lw * 2]) |
                      ((uint32_t)__bfloat16_as_ushort(u->p.ftl[dd][lw * 2 + 1]) << 16);
        size_t to = ((size_t)b * 64 + dd) * LL + l0 + lw * 2;
        *(uint32_t*)&g_Fth[to] = vh;
        *(uint32_t*)&g_Ftl[to] = vl;
    }
}

__device__ void do_xprep(SmemU1* u, int cta, const float* __restrict__ bx) {
    int iT = cta & 31;
    int hT = (cta >> 5) % 24;
    int b  = cta / (32 * 24);
    int i0 = iT * 64, h0 = hT * 32;
    int tid = threadIdx.x;

#pragma unroll
    for (int k = 0; k < 8; k++) {
        int idx = k * 256 + tid;
        int l = idx >> 5, h = idx & 31;
        u->x.t[h][l] = bx[((size_t)b * LL + i0 + l) * HH + h0 + h];
    }
    __syncthreads();

#pragma unroll
    for (int k = 0; k < 4; k++) {
        int idx = k * 256 + tid;
        int h = idx >> 5, lp = idx & 31;
        uint32_t hi, lo;
        split2pack(u->x.t[h][lp * 2], u->x.t[h][lp * 2 + 1], hi, lo);
        size_t off = ((size_t)b * HH + h0 + h) * LL + i0 + lp * 2;
        *(uint32_t*)&g_Xh[off] = hi;
        *(uint32_t*)&g_Xl[off] = lo;
    }
}

__global__ void __launch_bounds__(256) k_fat1(const float* __restrict__ ae,
                                              const void* __restrict__ xraw,
                                              const float* __restrict__ w,
                                              const float* __restrict__ bx) {
    __shared__ SmemU1 u;
    int cta = blockIdx.x;
    if (cta < 512) do_prep(&u, cta, ae, xraw, w);
    else           do_xprep(&u, cta - 512, bx);
}

// ---------------------------------------------------------------------------
// FAT KERNEL 2: pgen (CTAs 0..255) ∪ chunksum (CTAs 256..1791). 256 threads.
// ---------------------------------------------------------------------------
#define K2_ST    55296
#define K2_AH(s) ((s) * K2_ST)
#define K2_AL(s) ((s) * K2_ST + TILE)
#define K2_BH(s) ((s) * K2_ST + 2 * TILE)
#define K2_BL(s) ((s) * K2_ST + 2 * TILE + 9216)
#define K2_SMEM  (2 * K2_ST)

__device__ void do_pgen(char* smem, int cta) {
    uint32_t sb = smem_u32(smem);
    int tid = threadIdx.x, wid = tid >> 5, l = tid & 31;
    int c = cta & (NC - 1), b = cta >> 4;
    int jBase = c * CC;
    int wm = wid & 1, wn = wid >> 1;
    int fRow = tid >> 3, fCol = tid & 7;
    uint32_t fOff = (uint32_t)(fRow * STRB + fCol * 16);

    size_t eBase = ((size_t)b * LL + jBase) * 64;
#pragma unroll
    for (int v = 0; v < 4; v++) {
        uint32_t so = fOff + (uint32_t)(v * 32 * STRB);
        size_t go = eBase + (size_t)(fRow + v * 32) * 64 + fCol * 8;
        cp16(sb + 0 * TILE + so, g_Eph + go);
        cp16(sb + 1 * TILE + so, g_Epl + go);
        cp16(sb + 2 * TILE + so, g_Fph + go);
        cp16(sb + 3 * TILE + so, g_Fpl + go);
    }
    CP_COMMIT();
    CP_WAIT(0);
    __syncthreads();

    uint32_t aLane = (uint32_t)((wm * 64 + (l & 15)) * STRB + (l >> 4) * 16);
    uint32_t xLane = (uint32_t)((wn * 32 + (l & 7) + ((l >> 4) * 8)) * STRB +
                                ((l >> 3) & 1) * 16);

    float acc[4][4][4];
#pragma unroll
    for (int m = 0; m < 4; m++)
#pragma unroll
        for (int n = 0; n < 4; n++)
#pragma unroll
            for (int k = 0; k < 4; k++) acc[m][n][k] = 0.f;

    gemm4t<4>(acc, sb + 0 * TILE + aLane, sb + 1 * TILE + aLane,
              sb + 2 * TILE + xLane, sb + 3 * TILE + xLane, 16 * STRB);

    __nv_bfloat16* Ph = g_Ph + ((size_t)(b * NC + c)) * CC * CC;
    __nv_bfloat16* Pl = g_Pl + ((size_t)(b * NC + c)) * CC * CC;
#pragma unroll
    for (int m = 0; m < 4; m++) {
#pragma unroll
        for (int n = 0; n < 4; n++) {
            int gm = wm * 64 + m * 16 + (l >> 2);
            int gn = wn * 32 + n * 8 + (l & 3) * 2;
            float v0 = (gn < gm) ? acc[m][n][0] : 0.f;
            float v1 = (gn + 1 < gm) ? acc[m][n][1] : 0.f;
            float v2 = (gn < gm + 8) ? acc[m][n][2] : 0.f;
            float v3 = (gn + 1 < gm + 8) ? acc[m][n][3] : 0.f;
            uint32_t hi, lo;
            split2pack(v0, v1, hi, lo);
            *(uint32_t*)(Ph + (size_t)gm * CC + gn) = hi;
            *(uint32_t*)(Pl + (size_t)gm * CC + gn) = lo;
            split2pack(v2, v3, hi, lo);
            *(uint32_t*)(Ph + (size_t)(gm + 8) * CC + gn) = hi;
            *(uint32_t*)(Pl + (size_t)(gm + 8) * CC + gn) = lo;
        }
    }
}

__device__ void do_chunksum(char* smem, int cta) {
    uint32_t sb = smem_u32(smem);
    int tid = threadIdx.x, wid = tid >> 5, l = tid & 31;
    int hT = cta % 6;
    int c  = (cta / 6) & (NC - 1);
    int b  = cta / (6 * NC);
    int hBase = hT * 128;
    int wm = wid & 3, wn = wid >> 2;

    float acc[2][4][4];
#pragma unroll
    for (int m = 0; m < 2; m++)
#pragma unroll
        for (int n = 0; n < 4; n++)
#pragma unroll
            for (int k = 0; k < 4; k++) acc[m][n][k] = 0.f;

    uint32_t aLane = (uint32_t)((wm * 32 + (l & 15)) * STRB + (l >> 4) * 16);
    uint32_t xLane = (uint32_t)((wn * 32 + (l & 7) + ((l >> 4) * 8)) * STRB +
                                ((l >> 3) & 1) * 16);

#pragma unroll
    for (int st = 0; st < 2; st++) {
        size_t kOff = (size_t)c * CC + st * 64;
#pragma unroll
        for (int v = 0; v < 4; v++) {
            int idx = v * 256 + tid;
            int row = idx >> 3, col = idx & 7;
            uint32_t so = (uint32_t)(row * STRB + col * 16);
            size_t go = ((size_t)(b * HH + hBase + row)) * LL + kOff + col * 8;
            cp16(sb + K2_AH(st) + so, g_Xh + go);
            cp16(sb + K2_AL(st) + so, g_Xl + go);
        }
#pragma unroll
        for (int v = 0; v < 2; v++) {
            int idx = v * 256 + tid;
            int row = idx >> 3, col = idx & 7;
            uint32_t so = (uint32_t)(row * STRB + col * 16);
            size_t go = ((size_t)(b * DD + row)) * LL + kOff + col * 8;
            cp16(sb + K2_BH(st) + so, g_Fth + go);
            cp16(sb + K2_BL(st) + so, g_Ftl + go);
        }
        CP_COMMIT();
    }

#pragma unroll
    for (int st = 0; st < 2; st++) {
        if (st == 0) { CP_WAIT(1); } else { CP_WAIT(0); }
        __syncthreads();
        gemm4t<2>(acc, sb + K2_AH(st) + aLane, sb + K2_AL(st) + aLane,
                  sb + K2_BH(st) + xLane, sb + K2_BL(st) + xLane, 16 * STRB);
    }

    float* Tp = g_T + ((size_t)(b * NC + c)) * HH * DD;
#pragma unroll
    for (int m = 0; m < 2; m++) {
#pragma unroll
        for (int n = 0; n < 4; n++) {
            int gm = hBase + wm * 32 + m * 16 + (l >> 2);
            int gn = wn * 32 + n * 8 + (l & 3) * 2;
            *(float2*)(Tp + (size_t)gm * 64 + gn) =
                make_float2(acc[m][n][0], acc[m][n][1]);
            *(float2*)(Tp + (size_t)(gm + 8) * 64 + gn) =
                make_float2(acc[m][n][2], acc[m][n][3]);
        }
    }
}

__global__ void __launch_bounds__(256) k_fat2() {
    extern __shared__ char smem[];
    int cta = blockIdx.x;
    if (cta < 256) do_pgen(smem, cta);
    else           do_chunksum(smem, cta - 256);
}

// ---------------------------------------------------------------------------
// K3: exclusive prefix over chunks (float4 per thread)
// ---------------------------------------------------------------------------
__global__ void __launch_bounds__(256) k_prefix() {
    int b = blockIdx.y;
    int hd = (blockIdx.x * 256 + threadIdx.x) * 4;
    float4 run = make_float4(0.f, 0.f, 0.f, 0.f);
#pragma unroll
    for (int c = 0; c < NC; c++) {
        size_t o = ((size_t)(b * NC + c)) * HH * DD + hd;
        uint32_t h0, l0, h1, l1;
        split2pack(run.x, run.y, h0, l0);
        split2pack(run.z, run.w, h1, l1);
        *(uint2*)&g_Sh[o] = make_uint2(h0, h1);
        *(uint2*)&g_Sl[o] = make_uint2(l0, l1);
        float4 t = *(const float4*)&g_T[o];
        run.x += t.x; run.y += t.y; run.z += t.z; run.w += t.w;
    }
}

// ---------------------------------------------------------------------------
// K4 (R14 staged schedule, 512 threads) + L2 prefetch of epilogue bx tile
// ---------------------------------------------------------------------------
#define OFF_EH  0
#define OFF_EL  TILE
#define OFF_SH  (2 * TILE)
#define OFF_SL  (3 * TILE)
#define OFF_X0H (4 * TILE)
#define OFF_X0L (5 * TILE)
#define OFF_PH  (6 * TILE)
#define OFF_PL  (6 * TILE + PTILE)
#define K4_SMEM (6 * TILE + 2 * PTILE)

__global__ void __launch_bounds__(512, 1) k_apply2(const float* __restrict__ bx,
                                                   float* __restrict__ out) {
    extern __shared__ char smem[];
    uint32_t sb = smem_u32(smem);
    int tid = threadIdx.x, wid = tid >> 5, l = tid & 31;
    int hT = blockIdx.x, c = blockIdx.y, b = blockIdx.z;
    int hBase = hT * 128, jBase = c * CC;
    int wm = wid & 3, wn = wid >> 2;

    int fRow = tid >> 3, fCol = tid & 7;
    uint32_t fOff = (uint32_t)(fRow * STRB + fCol * 16);

    // G0: E' + S
    {
        size_t eBase = ((size_t)b * LL + jBase) * 64;
        size_t sBase = (((size_t)(b * NC + c)) * HH + hBase) * 64;
#pragma unroll
        for (int v = 0; v < 2; v++) {
            uint32_t so = fOff + (uint32_t)(v * 64 * STRB);
            size_t ge = eBase + (size_t)(fRow + v * 64) * 64 + fCol * 8;
            size_t gs = sBase + (size_t)(fRow + v * 64) * 64 + fCol * 8;
            cp16(sb + OFF_EH + so, g_Eph + ge);
            cp16(sb + OFF_EL + so, g_Epl + ge);
            cp16(sb + OFF_SH + so, g_Sh + gs);
            cp16(sb + OFF_SL + so, g_Sl + gs);
        }
        CP_COMMIT();
    }
    // G1: Xt sub0
    {
        size_t xBase = ((size_t)(b * HH + hBase)) * LL + jBase;
#pragma unroll
        for (int v = 0; v < 2; v++) {
            uint32_t so = fOff + (uint32_t)(v * 64 * STRB);
            size_t go = xBase + (size_t)(fRow + v * 64) * LL + fCol * 8;
            cp16(sb + OFF_X0H + so, g_Xh + go);
            cp16(sb + OFF_X0L + so, g_Xl + go);
        }
        CP_COMMIT();
    }
    // G2: P (hi/lo)
    {
        const __nv_bfloat16* Ph = g_Ph + ((size_t)(b * NC + c)) * CC * CC;
        const __nv_bfloat16* Pl = g_Pl + ((size_t)(b * NC + c)) * CC * CC;
#pragma unroll
        for (int v = 0; v < 4; v++) {
            int idx = v * 512 + tid;
            int row = idx >> 4, col = idx & 15;
            uint32_t so = (uint32_t)(row * STRP + col * 16);
            size_t go = (size_t)row * CC + col * 8;
            cp16(sb + OFF_PH + so, Ph + go);
            cp16(sb + OFF_PL + so, Pl + go);
        }
        CP_COMMIT();
    }

    // L2 prefetch of the epilogue bx tile (128 rows x 512B = 512 lines of 128B).
    // No registers consumed; converts end-of-kernel DRAM stalls into L2 hits.
    {
        int row = tid >> 2, seg = tid & 3;   // 512 threads -> one line each
        prefetchL2(bx + ((size_t)b * LL + jBase + row) * HH + hBase + seg * 32);
    }

    uint32_t aLane  = (uint32_t)((wm * 32 + (l & 15)) * STRB + (l >> 4) * 16);
    uint32_t aLaneP = (uint32_t)((wm * 32 + (l & 15)) * STRP + (l >> 4) * 16);
    uint32_t xLane  = (uint32_t)((wn * 32 + (l & 7) + ((l >> 4) * 8)) * STRB +
                                 ((l >> 3) & 1) * 16);

    float acc[2][4][4];
#pragma unroll
    for (int m = 0; m < 2; m++)
#pragma unroll
        for (int n = 0; n < 4; n++)
#pragma unroll
            for (int k = 0; k < 4; k++) acc[m][n][k] = 0.f;

    // ---- C1: acc += E' @ S^T ----
    CP_WAIT(2);
    __syncthreads();
    gemm4t<2>(acc, sb + OFF_EH + aLane, sb + OFF_EL + aLane,
              sb + OFF_SH + xLane, sb + OFF_SL + xLane, 16 * STRB);
    __syncthreads();

    // G3: Xt sub1 into E' space
    {
        size_t xBase = ((size_t)(b * HH + hBase)) * LL + jBase + 64;
#pragma unroll
        for (int v = 0; v < 2; v++) {
            uint32_t so = fOff + (uint32_t)(v * 64 * STRB);
            size_t go = xBase + (size_t)(fRow + v * 64) * LL + fCol * 8;
            cp16(sb + OFF_EH + so, g_Xh + go);
            cp16(sb + OFF_EL + so, g_Xl + go);
        }
        CP_COMMIT();
    }

    // ---- C2a: acc += P[:,0:64] @ X0^T ----
    CP_WAIT(1);
    __syncthreads();
    gemm4t<2>(acc, sb + OFF_PH + aLaneP, sb + OFF_PL + aLaneP,
              sb + OFF_X0H + xLane, sb + OFF_X0L + xLane, 16 * STRP);

    // ---- C2b: acc += P[:,64:128] @ X1^T ----
    CP_WAIT(0);
    __syncthreads();
    gemm4t<2>(acc, sb + OFF_PH + aLaneP + 128, sb + OFF_PL + aLaneP + 128,
              sb + OFF_EH + xLane, sb + OFF_EL + xLane, 16 * STRP);

    // ---- epilogue ----
#pragma unroll
    for (int m = 0; m < 2; m++) {
#pragma unroll
        for (int n = 0; n < 4; n++) {
            int gj = jBase + wm * 32 + m * 16 + (l >> 2);
            int gh = hBase + wn * 32 + n * 8 + (l & 3) * 2;
            size_t o0 = ((size_t)b * LL + gj) * HH + gh;
            size_t o1 = ((size_t)b * LL + gj + 8) * HH + gh;
            float2 x0 = *(const float2*)(bx + o0);
            float2 x1 = *(const float2*)(bx + o1);
            *(float2*)(out + o0) = make_float2(x0.x + acc[m][n][0], x0.y + acc[m][n][1]);
            *(float2*)(out + o1) = make_float2(x1.x + acc[m][n][2], x1.y + acc[m][n][3]);
        }
    }
}

// ---------------------------------------------------------------------------
extern "C" void kernel_launch(void* const* d_in, const int* in_sizes, int n_in,
                              void* d_out, int out_size) {
    const float* bert_x = nullptr;
    const void*  x      = nullptr;
    const float* ae     = nullptr;
    const float* w      = nullptr;
    for (int i = 0; i < n_in; i++) {
        switch (in_sizes[i]) {
            case 25165824: bert_x = (const float*)d_in[i]; break;
            case 32768:    x      = d_in[i];               break;
            case 1920000:  ae     = (const float*)d_in[i]; break;
            case 4096:     w      = (const float*)d_in[i]; break;
            default: break;
        }
    }
    float* out = (float*)d_out;

    cudaFuncSetAttribute(k_fat2,
                         cudaFuncAttributeMaxDynamicSharedMemorySize, K2_SMEM);
    cudaFuncSetAttribute(k_apply2,
                         cudaFuncAttributeMaxDynamicSharedMemorySize, K4_SMEM);

    k_fat1<<<512 + 12288, 256>>>(ae, x, w, bert_x);
    k_fat2<<<256 + 1536, 256, K2_SMEM>>>();
    k_prefix<<<dim3(HH * DD / 1024, BB), 256>>>();
    k_apply2<<<dim3(HH / 128, NC, BB), 512, K4_SMEM>>>(bert_x, out);
}

// round 17
// speedup vs baseline: 1.0802x; 1.0555x over previous
#include <cuda_runtime.h>
#include <cuda_bf16.h>
#include <cstdint>

#define BB 16
#define LL 2048
#define HH 768
#define DD 64
#define VV 30000
#define CC 128               // chunk length
#define NC 16                // number of chunks

// ---------------------------------------------------------------------------
// Device-global scratch
// ---------------------------------------------------------------------------
__device__ __nv_bfloat16 g_Eph[(size_t)BB * LL * DD];
__device__ __nv_bfloat16 g_Epl[(size_t)BB * LL * DD];
__device__ __nv_bfloat16 g_Fph[(size_t)BB * LL * DD];
__device__ __nv_bfloat16 g_Fpl[(size_t)BB * LL * DD];
__device__ __nv_bfloat16 g_Fth[(size_t)BB * DD * LL];
__device__ __nv_bfloat16 g_Ftl[(size_t)BB * DD * LL];
__device__ __nv_bfloat16 g_Xh[(size_t)BB * HH * LL];
__device__ __nv_bfloat16 g_Xl[(size_t)BB * HH * LL];
__device__ float         g_T [(size_t)BB * NC * HH * DD];
__device__ __nv_bfloat16 g_Sh[(size_t)BB * NC * HH * DD];
__device__ __nv_bfloat16 g_Sl[(size_t)BB * NC * HH * DD];
__device__ __nv_bfloat16 g_Ph[(size_t)BB * NC * CC * CC];
__device__ __nv_bfloat16 g_Pl[(size_t)BB * NC * CC * CC];

// ---------------------------------------------------------------------------
// helpers
// ---------------------------------------------------------------------------
__device__ __forceinline__ uint32_t smem_u32(const void* p) {
    uint32_t a;
    asm("{ .reg .u64 t; cvta.to.shared.u64 t, %1; cvt.u32.u64 %0, t; }"
        : "=r"(a) : "l"(p));
    return a;
}
__device__ __forceinline__ void ldm_x4(uint32_t& r0, uint32_t& r1, uint32_t& r2,
                                       uint32_t& r3, uint32_t addr) {
    asm volatile("ldmatrix.sync.aligned.m8n8.x4.shared.b16 {%0,%1,%2,%3}, [%4];"
                 : "=r"(r0), "=r"(r1), "=r"(r2), "=r"(r3) : "r"(addr));
}
__device__ __forceinline__ void mma16816(float* c, uint32_t a0, uint32_t a1,
                                         uint32_t a2, uint32_t a3, uint32_t b0,
                                         uint32_t b1) {
    asm volatile(
        "mma.sync.aligned.m16n8k16.row.col.f32.bf16.bf16.f32 "
        "{%0,%1,%2,%3}, {%4,%5,%6,%7}, {%8,%9}, {%0,%1,%2,%3};"
        : "+f"(c[0]), "+f"(c[1]), "+f"(c[2]), "+f"(c[3])
        : "r"(a0), "r"(a1), "r"(a2), "r"(a3), "r"(b0), "r"(b1));
}
__device__ __forceinline__ void cp16(uint32_t s, const void* g) {
    asm volatile("cp.async.cg.shared.global [%0], [%1], 16;" :: "r"(s), "l"(g));
}
#define CP_COMMIT()  asm volatile("cp.async.commit_group;" ::: "memory")
#define CP_WAIT(n)   asm volatile("cp.async.wait_group %0;" :: "n"(n) : "memory")

__device__ __forceinline__ void st_cs_f2(float* p, float a, float b) {
    asm volatile("st.global.cs.v2.f32 [%0], {%1, %2};" :: "l"(p), "f"(a), "f"(b)
                 : "memory");
}

__device__ __forceinline__ void split2pack(float a, float b, uint32_t& hi,
                                           uint32_t& lo) {
    __nv_bfloat16 ha = __float2bfloat16(a), hb = __float2bfloat16(b);
    __nv_bfloat16 la = __float2bfloat16(a - __bfloat162float(ha));
    __nv_bfloat16 lb = __float2bfloat16(b - __bfloat162float(hb));
    hi = (uint32_t)__bfloat16_as_ushort(ha) |
         ((uint32_t)__bfloat16_as_ushort(hb) << 16);
    lo = (uint32_t)__bfloat16_as_ushort(la) |
         ((uint32_t)__bfloat16_as_ushort(lb) << 16);
}

#define STRB  144
#define TILE  18432
#define STRP  272
#define PTILE 34816

template <int MF>
__device__ __forceinline__ void gemm4t(float (&acc)[MF][4][4], uint32_t aH,
                                       uint32_t aL, uint32_t bH, uint32_t bL,
                                       uint32_t aMstr) {
#pragma unroll
    for (int s = 0; s < 4; s++) {
        uint32_t ks = (uint32_t)(s * 32);
        uint32_t bhf[8], blf[8];
        ldm_x4(bhf[0], bhf[1], bhf[2], bhf[3], bH + ks);
        ldm_x4(bhf[4], bhf[5], bhf[6], bhf[7], bH + ks + 16 * STRB);
        ldm_x4(blf[0], blf[1], blf[2], blf[3], bL + ks);
        ldm_x4(blf[4], blf[5], blf[6], blf[7], bL + ks + 16 * STRB);
#pragma unroll
        for (int m = 0; m < MF; m++) {
            uint32_t ah0, ah1, ah2, ah3, al0, al1, al2, al3;
            ldm_x4(ah0, ah1, ah2, ah3, aH + m * aMstr + ks);
            ldm_x4(al0, al1, al2, al3, aL + m * aMstr + ks);
#pragma unroll
            for (int n = 0; n < 4; n++) {
                uint32_t i0 = (uint32_t)((n >> 1) * 4 + (n & 1) * 2);
                mma16816(acc[m][n], ah0, ah1, ah2, ah3, bhf[i0], bhf[i0 + 1]);
                mma16816(acc[m][n], ah0, ah1, ah2, ah3, blf[i0], blf[i0 + 1]);
                mma16816(acc[m][n], al0, al1, al2, al3, bhf[i0], bhf[i0 + 1]);
            }
        }
    }
}

// ---------------------------------------------------------------------------
// FAT KERNEL 1: prep (CTAs 0..511) ∪ xprep (CTAs 512..12799). 256 threads.
// ---------------------------------------------------------------------------
union SmemU1 {
    struct {
        float ws[64 * 64];
        float es[4][64];
        __nv_bfloat16 fth[64][66];
        __nv_bfloat16 ftl[64][66];
    } p;
    struct {
        float t[32][65];
    } x;
};

__device__ void do_prep(SmemU1* u, int cta, const float* __restrict__ ae,
                        const void* __restrict__ xraw, const float* __restrict__ w) {
    for (int t = threadIdx.x; t < 64 * 64; t += 256) u->p.ws[t] = w[t];

    const int* xi = (const int*)xraw;
    bool is64 = true;
#pragma unroll
    for (int k = 0; k < 32; k++)
        if (xi[2 * k + 1] != 0) is64 = false;

    int sub = threadIdx.x >> 6;
    int d   = threadIdx.x & 63;

    int rowBase = cta * 64;
    int b  = rowBase >> 11;
    int l0 = rowBase & (LL - 1);

    for (int it = 0; it < 16; it++) {
        int lloc = it * 4 + sub;
        int row = rowBase + lloc;
        int l = l0 + lloc;

        long long tok;
        if (is64) tok = ((const long long*)xraw)[row];
        else      tok = (long long)xi[row];
        if (tok < 0) tok = 0;
        if (tok >= VV) tok = VV - 1;

        float e = ae[(size_t)tok * 64 + d];
        __syncthreads();
        u->p.es[sub][d] = e;
        __syncthreads();
        float f = 0.f;
#pragma unroll
        for (int k = 0; k < 64; k++) f += u->p.es[sub][k] * u->p.ws[k * 64 + d];

        float sc = (float)(l + 1);
        float ep = e / sc;
        float fp = f * sc;

        __nv_bfloat16 eh = __float2bfloat16(ep);
        __nv_bfloat16 el = __float2bfloat16(ep - __bfloat162float(eh));
        __nv_bfloat16 fh = __float2bfloat16(fp);
        __nv_bfloat16 fl = __float2bfloat16(fp - __bfloat162float(fh));

        size_t ro = (size_t)row * 64 + d;
        g_Eph[ro] = eh; g_Epl[ro] = el;
        g_Fph[ro] = fh; g_Fpl[ro] = fl;
        u->p.fth[d][lloc] = fh;
        u->p.ftl[d][lloc] = fl;
    }
    __syncthreads();

    for (int k = 0; k < 8; k++) {
        int idx = k * 256 + threadIdx.x;
        int dd = idx >> 5, lw = idx & 31;
        uint32_t vh = (uint32_t)__bfloat16_as_ushort(u->p.fth[dd][lw * 2]) |
                      ((uint32_t)__bfloat16_as_ushort(u->p.fth[dd][lw * 2 + 1]) << 16);
        uint32_t vl = (uint32_t)__bfloat16_as_ushort(u->p.ftl[dd][lw * 2]) |
                      ((uint32_t)__bfloat16_as_ushort(u->p.ftl[dd][lw * 2 + 1]) << 16);
        size_t to = ((size_t)b * 64 + dd) * LL + l0 + lw * 2;
        *(uint32_t*)&g_Fth[to] = vh;
        *(uint32_t*)&g_Ftl[to] = vl;
    }
}

__device__ void do_xprep(SmemU1* u, int cta, const float* __restrict__ bx) {
    int iT = cta & 31;
    int hT = (cta >> 5) % 24;
    int b  = cta / (32 * 24);
    int i0 = iT * 64, h0 = hT * 32;
    int tid = threadIdx.x;

#pragma unroll
    for (int k = 0; k < 8; k++) {
        int idx = k * 256 + tid;
        int l = idx >> 5, h = idx & 31;
        u->x.t[h][l] = bx[((size_t)b * LL + i0 + l) * HH + h0 + h];
    }
    __syncthreads();

#pragma unroll
    for (int k = 0; k < 4; k++) {
        int idx = k * 256 + tid;
        int h = idx >> 5, lp = idx & 31;
        uint32_t hi, lo;
        split2pack(u->x.t[h][lp * 2], u->x.t[h][lp * 2 + 1], hi, lo);
        size_t off = ((size_t)b * HH + h0 + h) * LL + i0 + lp * 2;
        *(uint32_t*)&g_Xh[off] = hi;
        *(uint32_t*)&g_Xl[off] = lo;
    }
}

__global__ void __launch_bounds__(256) k_fat1(const float* __restrict__ ae,
                                              const void* __restrict__ xraw,
                                              const float* __restrict__ w,
                                              const float* __restrict__ bx) {
    __shared__ SmemU1 u;
    int cta = blockIdx.x;
    if (cta < 512) do_prep(&u, cta, ae, xraw, w);
    else           do_xprep(&u, cta - 512, bx);
}

// ---------------------------------------------------------------------------
// FAT KERNEL 2: pgen (CTAs 0..255) ∪ chunksum (CTAs 256..1791). 256 threads.
// ---------------------------------------------------------------------------
#define K2_ST    55296
#define K2_AH(s) ((s) * K2_ST)
#define K2_AL(s) ((s) * K2_ST + TILE)
#define K2_BH(s) ((s) * K2_ST + 2 * TILE)
#define K2_BL(s) ((s) * K2_ST + 2 * TILE + 9216)
#define K2_SMEM  (2 * K2_ST)

__device__ void do_pgen(char* smem, int cta) {
    uint32_t sb = smem_u32(smem);
    int tid = threadIdx.x, wid = tid >> 5, l = tid & 31;
    int c = cta & (NC - 1), b = cta >> 4;
    int jBase = c * CC;
    int wm = wid & 1, wn = wid >> 1;
    int fRow = tid >> 3, fCol = tid & 7;
    uint32_t fOff = (uint32_t)(fRow * STRB + fCol * 16);

    size_t eBase = ((size_t)b * LL + jBase) * 64;
#pragma unroll
    for (int v = 0; v < 4; v++) {
        uint32_t so = fOff + (uint32_t)(v * 32 * STRB);
        size_t go = eBase + (size_t)(fRow + v * 32) * 64 + fCol * 8;
        cp16(sb + 0 * TILE + so, g_Eph + go);
        cp16(sb + 1 * TILE + so, g_Epl + go);
        cp16(sb + 2 * TILE + so, g_Fph + go);
        cp16(sb + 3 * TILE + so, g_Fpl + go);
    }
    CP_COMMIT();
    CP_WAIT(0);
    __syncthreads();

    uint32_t aLane = (uint32_t)((wm * 64 + (l & 15)) * STRB + (l >> 4) * 16);
    uint32_t xLane = (uint32_t)((wn * 32 + (l & 7) + ((l >> 4) * 8)) * STRB +
                                ((l >> 3) & 1) * 16);

    float acc[4][4][4];
#pragma unroll
    for (int m = 0; m < 4; m++)
#pragma unroll
        for (int n = 0; n < 4; n++)
#pragma unroll
            for (int k = 0; k < 4; k++) acc[m][n][k] = 0.f;

    gemm4t<4>(acc, sb + 0 * TILE + aLane, sb + 1 * TILE + aLane,
              sb + 2 * TILE + xLane, sb + 3 * TILE + xLane, 16 * STRB);

    __nv_bfloat16* Ph = g_Ph + ((size_t)(b * NC + c)) * CC * CC;
    __nv_bfloat16* Pl = g_Pl + ((size_t)(b * NC + c)) * CC * CC;
#pragma unroll
    for (int m = 0; m < 4; m++) {
#pragma unroll
        for (int n = 0; n < 4; n++) {
            int gm = wm * 64 + m * 16 + (l >> 2);
            int gn = wn * 32 + n * 8 + (l & 3) * 2;
            float v0 = (gn < gm) ? acc[m][n][0] : 0.f;
            float v1 = (gn + 1 < gm) ? acc[m][n][1] : 0.f;
            float v2 = (gn < gm + 8) ? acc[m][n][2] : 0.f;
            float v3 = (gn + 1 < gm + 8) ? acc[m][n][3] : 0.f;
            uint32_t hi, lo;
            split2pack(v0, v1, hi, lo);
            *(uint32_t*)(Ph + (size_t)gm * CC + gn) = hi;
            *(uint32_t*)(Pl + (size_t)gm * CC + gn) = lo;
            split2pack(v2, v3, hi, lo);
            *(uint32_t*)(Ph + (size_t)(gm + 8) * CC + gn) = hi;
            *(uint32_t*)(Pl + (size_t)(gm + 8) * CC + gn) = lo;
        }
    }
}

__device__ void do_chunksum(char* smem, int cta) {
    uint32_t sb = smem_u32(smem);
    int tid = threadIdx.x, wid = tid >> 5, l = tid & 31;
    int hT = cta % 6;
    int c  = (cta / 6) & (NC - 1);
    int b  = cta / (6 * NC);
    int hBase = hT * 128;
    int wm = wid & 3, wn = wid >> 2;

    float acc[2][4][4];
#pragma unroll
    for (int m = 0; m < 2; m++)
#pragma unroll
        for (int n = 0; n < 4; n++)
#pragma unroll
            for (int k = 0; k < 4; k++) acc[m][n][k] = 0.f;

    uint32_t aLane = (uint32_t)((wm * 32 + (l & 15)) * STRB + (l >> 4) * 16);
    uint32_t xLane = (uint32_t)((wn * 32 + (l & 7) + ((l >> 4) * 8)) * STRB +
                                ((l >> 3) & 1) * 16);

#pragma unroll
    for (int st = 0; st < 2; st++) {
        size_t kOff = (size_t)c * CC + st * 64;
#pragma unroll
        for (int v = 0; v < 4; v++) {
            int idx = v * 256 + tid;
            int row = idx >> 3, col = idx & 7;
            uint32_t so = (uint32_t)(row * STRB + col * 16);
            size_t go = ((size_t)(b * HH + hBase + row)) * LL + kOff + col * 8;
            cp16(sb + K2_AH(st) + so, g_Xh + go);
            cp16(sb + K2_AL(st) + so, g_Xl + go);
        }
#pragma unroll
        for (int v = 0; v < 2; v++) {
            int idx = v * 256 + tid;
            int row = idx >> 3, col = idx & 7;
            uint32_t so = (uint32_t)(row * STRB + col * 16);
            size_t go = ((size_t)(b * DD + row)) * LL + kOff + col * 8;
            cp16(sb + K2_BH(st) + so, g_Fth + go);
            cp16(sb + K2_BL(st) + so, g_Ftl + go);
        }
        CP_COMMIT();
    }

#pragma unroll
    for (int st = 0; st < 2; st++) {
        if (st == 0) { CP_WAIT(1); } else { CP_WAIT(0); }
        __syncthreads();
        gemm4t<2>(acc, sb + K2_AH(st) + aLane, sb + K2_AL(st) + aLane,
                  sb + K2_BH(st) + xLane, sb + K2_BL(st) + xLane, 16 * STRB);
    }

    float* Tp = g_T + ((size_t)(b * NC + c)) * HH * DD;
#pragma unroll
    for (int m = 0; m < 2; m++) {
#pragma unroll
        for (int n = 0; n < 4; n++) {
            int gm = hBase + wm * 32 + m * 16 + (l >> 2);
            int gn = wn * 32 + n * 8 + (l & 3) * 2;
            *(float2*)(Tp + (size_t)gm * 64 + gn) =
                make_float2(acc[m][n][0], acc[m][n][1]);
            *(float2*)(Tp + (size_t)(gm + 8) * 64 + gn) =
                make_float2(acc[m][n][2], acc[m][n][3]);
        }
    }
}

__global__ void __launch_bounds__(256) k_fat2() {
    extern __shared__ char smem[];
    int cta = blockIdx.x;
    if (cta < 256) do_pgen(smem, cta);
    else           do_chunksum(smem, cta - 256);
}

// ---------------------------------------------------------------------------
// K3: exclusive prefix over chunks (float4 per thread)
// ---------------------------------------------------------------------------
__global__ void __launch_bounds__(256) k_prefix() {
    int b = blockIdx.y;
    int hd = (blockIdx.x * 256 + threadIdx.x) * 4;
    float4 run = make_float4(0.f, 0.f, 0.f, 0.f);
#pragma unroll
    for (int c = 0; c < NC; c++) {
        size_t o = ((size_t)(b * NC + c)) * HH * DD + hd;
        uint32_t h0, l0, h1, l1;
        split2pack(run.x, run.y, h0, l0);
        split2pack(run.z, run.w, h1, l1);
        *(uint2*)&g_Sh[o] = make_uint2(h0, h1);
        *(uint2*)&g_Sl[o] = make_uint2(l0, l1);
        float4 t = *(const float4*)&g_T[o];
        run.x += t.x; run.y += t.y; run.z += t.z; run.w += t.w;
    }
}

// ---------------------------------------------------------------------------
// K4 (R14 staged schedule, 512 threads); out stores via st.global.cs
// ---------------------------------------------------------------------------
#define OFF_EH  0
#define OFF_EL  TILE
#define OFF_SH  (2 * TILE)
#define OFF_SL  (3 * TILE)
#define OFF_X0H (4 * TILE)
#define OFF_X0L (5 * TILE)
#define OFF_PH  (6 * TILE)
#define OFF_PL  (6 * TILE + PTILE)
#define K4_SMEM (6 * TILE + 2 * PTILE)

__global__ void __launch_bounds__(512, 1) k_apply2(const float* __restrict__ bx,
                                                   float* __restrict__ out) {
    extern __shared__ char smem[];
    uint32_t sb = smem_u32(smem);
    int tid = threadIdx.x, wid = tid >> 5, l = tid & 31;
    int hT = blockIdx.x, c = blockIdx.y, b = blockIdx.z;
    int hBase = hT * 128, jBase = c * CC;
    int wm = wid & 3, wn = wid >> 2;

    int fRow = tid >> 3, fCol = tid & 7;
    uint32_t fOff = (uint32_t)(fRow * STRB + fCol * 16);

    // G0: E' + S
    {
        size_t eBase = ((size_t)b * LL + jBase) * 64;
        size_t sBase = (((size_t)(b * NC + c)) * HH + hBase) * 64;
#pragma unroll
        for (int v = 0; v < 2; v++) {
            uint32_t so = fOff + (uint32_t)(v * 64 * STRB);
            size_t ge = eBase + (size_t)(fRow + v * 64) * 64 + fCol * 8;
            size_t gs = sBase + (size_t)(fRow + v * 64) * 64 + fCol * 8;
            cp16(sb + OFF_EH + so, g_Eph + ge);
            cp16(sb + OFF_EL + so, g_Epl + ge);
            cp16(sb + OFF_SH + so, g_Sh + gs);
            cp16(sb + OFF_SL + so, g_Sl + gs);
        }
        CP_COMMIT();
    }
    // G1: Xt sub0
    {
        size_t xBase = ((size_t)(b * HH + hBase)) * LL + jBase;
#pragma unroll
        for (int v = 0; v < 2; v++) {
            uint32_t so = fOff + (uint32_t)(v * 64 * STRB);
            size_t go = xBase + (size_t)(fRow + v * 64) * LL + fCol * 8;
            cp16(sb + OFF_X0H + so, g_Xh + go);
            cp16(sb + OFF_X0L + so, g_Xl + go);
        }
        CP_COMMIT();
    }
    // G2: P (hi/lo)
    {
        const __nv_bfloat16* Ph = g_Ph + ((size_t)(b * NC + c)) * CC * CC;
        const __nv_bfloat16* Pl = g_Pl + ((size_t)(b * NC + c)) * CC * CC;
#pragma unroll
        for (int v = 0; v < 4; v++) {
            int idx = v * 512 + tid;
            int row = idx >> 4, col = idx & 15;
            uint32_t so = (uint32_t)(row * STRP + col * 16);
            size_t go = (size_t)row * CC + col * 8;
            cp16(sb + OFF_PH + so, Ph + go);
            cp16(sb + OFF_PL + so, Pl + go);
        }
        CP_COMMIT();
    }

    uint32_t aLane  = (uint32_t)((wm * 32 + (l & 15)) * STRB + (l >> 4) * 16);
    uint32_t aLaneP = (uint32_t)((wm * 32 + (l & 15)) * STRP + (l >> 4) * 16);
    uint32_t xLane  = (uint32_t)((wn * 32 + (l & 7) + ((l >> 4) * 8)) * STRB +
                                 ((l >> 3) & 1) * 16);

    float acc[2][4][4];
#pragma unroll
    for (int m = 0; m < 2; m++)
#pragma unroll
        for (int n = 0; n < 4; n++)
#pragma unroll
            for (int k = 0; k < 4; k++) acc[m][n][k] = 0.f;

    // ---- C1: acc += E' @ S^T ----
    CP_WAIT(2);
    __syncthreads();
    gemm4t<2>(acc, sb + OFF_EH + aLane, sb + OFF_EL + aLane,
              sb + OFF_SH + xLane, sb + OFF_SL + xLane, 16 * STRB);
    __syncthreads();

    // G3: Xt sub1 into E' space
    {
        size_t xBase = ((size_t)(b * HH + hBase)) * LL + jBase + 64;
#pragma unroll
        for (int v = 0; v < 2; v++) {
            uint32_t so = fOff + (uint32_t)(v * 64 * STRB);
            size_t go = xBase + (size_t)(fRow + v * 64) * LL + fCol * 8;
            cp16(sb + OFF_EH + so, g_Xh + go);
            cp16(sb + OFF_EL + so, g_Xl + go);
        }
        CP_COMMIT();
    }

    // ---- C2a: acc += P[:,0:64] @ X0^T ----
    CP_WAIT(1);
    __syncthreads();
    gemm4t<2>(acc, sb + OFF_PH + aLaneP, sb + OFF_PL + aLaneP,
              sb + OFF_X0H + xLane, sb + OFF_X0L + xLane, 16 * STRP);

    // ---- C2b: acc += P[:,64:128] @ X1^T ----
    CP_WAIT(0);
    __syncthreads();
    gemm4t<2>(acc, sb + OFF_PH + aLaneP + 128, sb + OFF_PL + aLaneP + 128,
              sb + OFF_EH + xLane, sb + OFF_EL + xLane, 16 * STRP);

    // ---- epilogue (out via streaming stores: written once, never re-read) ----
#pragma unroll
    for (int m = 0; m < 2; m++) {
#pragma unroll
        for (int n = 0; n < 4; n++) {
            int gj = jBase + wm * 32 + m * 16 + (l >> 2);
            int gh = hBase + wn * 32 + n * 8 + (l & 3) * 2;
            size_t o0 = ((size_t)b * LL + gj) * HH + gh;
            size_t o1 = ((size_t)b * LL + gj + 8) * HH + gh;
            float2 x0 = *(const float2*)(bx + o0);
            float2 x1 = *(const float2*)(bx + o1);
            st_cs_f2(out + o0, x0.x + acc[m][n][0], x0.y + acc[m][n][1]);
            st_cs_f2(out + o1, x1.x + acc[m][n][2], x1.y + acc[m][n][3]);
        }
    }
}

// ---------------------------------------------------------------------------
extern "C" void kernel_launch(void* const* d_in, const int* in_sizes, int n_in,
                              void* d_out, int out_size) {
    const float* bert_x = nullptr;
    const void*  x      = nullptr;
    const float* ae     = nullptr;
    const float* w      = nullptr;
    for (int i = 0; i < n_in; i++) {
        switch (in_sizes[i]) {
            case 25165824: bert_x = (const float*)d_in[i]; break;
            case 32768:    x      = d_in[i];               break;
            case 1920000:  ae     = (const float*)d_in[i]; break;
            case 4096:     w      = (const float*)d_in[i]; break;
            default: break;
        }
    }
    float* out = (float*)d_out;

    cudaFuncSetAttribute(k_fat2,
                         cudaFuncAttributeMaxDynamicSharedMemorySize, K2_SMEM);
    cudaFuncSetAttribute(k_apply2,
                         cudaFuncAttributeMaxDynamicSharedMemorySize, K4_SMEM);

    k_fat1<<<512 + 12288, 256>>>(ae, x, w, bert_x);
    k_fat2<<<256 + 1536, 256, K2_SMEM>>>();
    k_prefix<<<dim3(HH * DD / 1024, BB), 256>>>();
    k_apply2<<<dim3(HH / 128, NC, BB), 512, K4_SMEM>>>(bert_x, out);
}